// round 1
// baseline (speedup 1.0000x reference)
#include <cuda_runtime.h>
#include <math.h>

// Problem constants
#define BB      32768
#define SS      8
#define DD      64
#define HH      4
#define LL      4
#define DHH     256
#define NB      8           // batches per CTA
#define NT      256         // threads per CTA
#define SCALE_ATT 0.125f    // 1/sqrt(64)
#define LN_EPS  1e-5f

// Output packing offsets (flat concat of return tuple, C-order)
#define OFF_COLOR 0
#define OFF_SIGMA (3 * BB)                       // 98304
#define OFF_OUT   (OFF_SIGMA + BB)               // 131072
#define OFF_ATTN  (OFF_OUT + (size_t)BB * 512)   // 16908288

// Shared memory layout (floats)
#define SX_OFF   0                      // [64][64]   x activations        (4096)
#define SCTX_OFF 4096                   // [64][256]  attention context    (16384)
#define ST_OFF   (4096 + 16384)         // 12288 temp: q/k/v | latent chunk | y
#define SW_OFF   (ST_OFF + 12288)       // 16384 weight staging
#define SP_OFF   (SW_OFF + 16384)       // 512 probs
#define SQI_OFF  (SP_OFF + 512)         // 512 query in
#define SCA_OFF  (SQI_OFF + 512)        // 512 cross-attn relu buffer
#define SMEM_FLOATS (SCA_OFF + 512)     // 50688 floats = 202752 bytes

typedef unsigned long long ull;

// ---- packed f32x2 helpers (FFMA2: 2 fp32 FMAs per instruction on sm_103a) ----
__device__ __forceinline__ ull pk2(float lo, float hi) {
    ull r;
    asm("mov.b64 %0, {%1, %2};" : "=l"(r) : "r"(__float_as_uint(lo)), "r"(__float_as_uint(hi)));
    return r;
}
__device__ __forceinline__ void fma2(ull &acc, ull a, ull b) {
    asm("fma.rn.f32x2 %0, %1, %2, %0;" : "+l"(acc) : "l"(a), "l"(b));
}
__device__ __forceinline__ float2 upk(ull v) {
    unsigned int lo, hi;
    asm("mov.b64 {%0, %1}, %2;" : "=r"(lo), "=r"(hi) : "l"(v));
    return make_float2(__uint_as_float(lo), __uint_as_float(hi));
}

// ---- cooperative copiers ----
__device__ __forceinline__ void cp_f4(float* __restrict__ dst, const float* __restrict__ src,
                                      int n4, int tid) {
    for (int i = tid; i < n4; i += NT)
        reinterpret_cast<float4*>(dst)[i] = reinterpret_cast<const float4*>(src)[i];
}
// copy a [64][64] head slice out of a [64][256] row-major matrix (src points at col h*64)
__device__ __forceinline__ void cp_slice(float* __restrict__ dst, const float* __restrict__ src,
                                         int tid) {
    for (int i = tid; i < 64 * 16; i += NT) {
        int r = i >> 4, c = i & 15;
        reinterpret_cast<float4*>(dst)[i] =
            reinterpret_cast<const float4*>(src + r * 256)[c];
    }
}

// ---- block GEMM core: Y[64][64] += X[64][LDX(K part)] @ W[K][64]  ----
// thread tile: 4 rows x 4 cols; packed f32x2 accumulation
template<int K, int LDX>
__device__ __forceinline__ void gemm_acc(const float* __restrict__ X,
                                         const float* __restrict__ W,
                                         ull a01[4], ull a23[4], int c0, int rb) {
#pragma unroll 8
    for (int k = 0; k < K; ++k) {
        float4 wv = *reinterpret_cast<const float4*>(W + k * 64 + c0);
        ull w01 = pk2(wv.x, wv.y);
        ull w23 = pk2(wv.z, wv.w);
#pragma unroll
        for (int r = 0; r < 4; ++r) {
            float xv = X[(rb + r) * LDX + k];
            ull xx = pk2(xv, xv);
            fma2(a01[r], w01, xx);
            fma2(a23[r], w23, xx);
        }
    }
}

template<int K, int LDX, bool RELU>
__device__ __forceinline__ void gemm_block(const float* __restrict__ X,
                                           const float* __restrict__ W,
                                           const float* __restrict__ bias,  // global, 64
                                           float* __restrict__ Y,           // [64][64] smem
                                           int tid) {
    const int c0 = (tid & 15) * 4;
    const int rb = (tid >> 4) * 4;
    ull a01[4] = {0, 0, 0, 0};
    ull a23[4] = {0, 0, 0, 0};
    gemm_acc<K, LDX>(X, W, a01, a23, c0, rb);
    float b0v = bias[c0], b1v = bias[c0 + 1], b2v = bias[c0 + 2], b3v = bias[c0 + 3];
#pragma unroll
    for (int r = 0; r < 4; ++r) {
        float2 v01 = upk(a01[r]);
        float2 v23 = upk(a23[r]);
        float o0 = v01.x + b0v, o1 = v01.y + b1v, o2 = v23.x + b2v, o3 = v23.y + b3v;
        if (RELU) {
            o0 = fmaxf(o0, 0.f); o1 = fmaxf(o1, 0.f);
            o2 = fmaxf(o2, 0.f); o3 = fmaxf(o3, 0.f);
        }
        float4 o = make_float4(o0, o1, o2, o3);
        *reinterpret_cast<float4*>(Y + (rb + r) * 64 + c0) = o;
    }
}

// ---- residual + LayerNorm: SX[r] = LN(Yd[r] + SX[r]) * g + be ; warp w handles rows w*8..w*8+7 ----
__device__ __forceinline__ void ln_block(const float* __restrict__ Yd, float* __restrict__ Xs,
                                         const float* __restrict__ g, const float* __restrict__ be,
                                         int w, int l) {
    float g0 = g[l], g1v = g[l + 32], e0 = be[l], e1v = be[l + 32];
#pragma unroll
    for (int i = 0; i < 8; ++i) {
        int r = w * 8 + i;
        float v0 = Yd[r * 64 + l]      + Xs[r * 64 + l];
        float v1 = Yd[r * 64 + 32 + l] + Xs[r * 64 + 32 + l];
        float s = v0 + v1;
#pragma unroll
        for (int o = 16; o >= 1; o >>= 1) s += __shfl_xor_sync(0xffffffffu, s, o);
        float m = s * (1.f / 64.f);
        float d0 = v0 - m, d1 = v1 - m;
        float q = d0 * d0 + d1 * d1;
#pragma unroll
        for (int o = 16; o >= 1; o >>= 1) q += __shfl_xor_sync(0xffffffffu, q, o);
        float inv = rsqrtf(q * (1.f / 64.f) + LN_EPS);
        Xs[r * 64 + l]      = d0 * inv * g0 + e0;
        Xs[r * 64 + 32 + l] = d1 * inv * g1v + e1v;
    }
}

extern "C" __global__ void __launch_bounds__(NT, 1)
radiance_kernel(const float* __restrict__ query, const float* __restrict__ latent,
                const float* __restrict__ W1, const float* __restrict__ b1,
                const float* __restrict__ Wq, const float* __restrict__ bq,
                const float* __restrict__ Wk, const float* __restrict__ bk,
                const float* __restrict__ Wv, const float* __restrict__ bv,
                const float* __restrict__ Wo, const float* __restrict__ bo,
                const float* __restrict__ fW1, const float* __restrict__ fb1,
                const float* __restrict__ fW2, const float* __restrict__ fb2,
                const float* __restrict__ g1, const float* __restrict__ be1,
                const float* __restrict__ g2, const float* __restrict__ be2,
                const float* __restrict__ cWq, const float* __restrict__ cbq,
                const float* __restrict__ cWk, const float* __restrict__ cbk,
                const float* __restrict__ cWv, const float* __restrict__ cbv,
                const float* __restrict__ cWo, const float* __restrict__ cbo,
                const float* __restrict__ Wc, const float* __restrict__ bc,
                const float* __restrict__ Ws, const float* __restrict__ bs,
                float* __restrict__ out) {
    extern __shared__ float smem[];
    float* SX   = smem + SX_OFF;     // [64][64]
    float* SCTX = smem + SCTX_OFF;   // [64][256]
    float* ST   = smem + ST_OFF;     // 12288
    float* SW   = smem + SW_OFF;     // 16384
    float* SP   = smem + SP_OFF;     // 512
    float* SQI  = smem + SQI_OFF;    // 512
    float* SCA  = smem + SCA_OFF;    // 512

    const int tid = threadIdx.x;
    const int w = tid >> 5;   // warp == local batch
    const int l = tid & 31;
    const int b0 = blockIdx.x * NB;

    float* attn_out = out + OFF_ATTN;

    // ================= Stage 0: x = relu(latent @ W1 + b1) =================
    {
        const int c0 = (tid & 15) * 4;
        const int rb = (tid >> 4) * 4;
        ull a01[4] = {0, 0, 0, 0};
        ull a23[4] = {0, 0, 0, 0};
        for (int ch = 0; ch < 4; ++ch) {
            __syncthreads();
            // W1 chunk rows ch*128..+128 -> SW (contiguous 8192 floats)
            cp_f4(SW, W1 + ch * 8192, 2048, tid);
            // latent chunk [64 rows][128] -> ST
            for (int i = tid; i < 2048; i += NT) {
                int r = i >> 5, j = i & 31;
                reinterpret_cast<float4*>(ST)[i] =
                    *reinterpret_cast<const float4*>(latent + (size_t)(b0 * 8 + r) * 512 + ch * 128 + j * 4);
            }
            __syncthreads();
            gemm_acc<128, 128>(ST, SW, a01, a23, c0, rb);
        }
        float b0v = b1[c0], b1v = b1[c0 + 1], b2v = b1[c0 + 2], b3v = b1[c0 + 3];
#pragma unroll
        for (int r = 0; r < 4; ++r) {
            float2 v01 = upk(a01[r]);
            float2 v23 = upk(a23[r]);
            float4 o = make_float4(fmaxf(v01.x + b0v, 0.f), fmaxf(v01.y + b1v, 0.f),
                                   fmaxf(v23.x + b2v, 0.f), fmaxf(v23.y + b3v, 0.f));
            *reinterpret_cast<float4*>(SX + (rb + r) * 64 + c0) = o;
        }
    }

    // ================= 4 transformer layers =================
    for (int li = 0; li < LL; ++li) {
        const float* Wq_i = Wq + li * 16384;
        const float* Wk_i = Wk + li * 16384;
        const float* Wv_i = Wv + li * 16384;
        const float* bq_i = bq + li * 256;
        const float* bk_i = bk + li * 256;
        const float* bv_i = bv + li * 256;

        for (int h = 0; h < HH; ++h) {
            __syncthreads();
            cp_slice(SW,        Wq_i + h * 64, tid);
            cp_slice(SW + 4096, Wk_i + h * 64, tid);
            cp_slice(SW + 8192, Wv_i + h * 64, tid);
            __syncthreads();
            gemm_block<64, 64, false>(SX, SW,        bq_i + h * 64, ST,        tid); // Q
            gemm_block<64, 64, false>(SX, SW + 4096, bk_i + h * 64, ST + 4096, tid); // K
            gemm_block<64, 64, false>(SX, SW + 8192, bv_i + h * 64, ST + 8192, tid); // V
            __syncthreads();

            // ---- attention per warp (= batch) ----
            {
                const float* qB = ST + w * 512;
                const float* kB = ST + 4096 + w * 512;
                const float* vB = ST + 8192 + w * 512;
                int qi = l >> 3, kj = l & 7;
                float s0 = 0.f, s1 = 0.f;
#pragma unroll 8
                for (int d = 0; d < 64; ++d) {
                    float kv = kB[kj * 64 + d];
                    s0 += qB[qi * 64 + d] * kv;
                    s1 += qB[(qi + 4) * 64 + d] * kv;
                }
                s0 *= SCALE_ATT; s1 *= SCALE_ATT;
                float m0 = s0, m1 = s1;
#pragma unroll
                for (int o = 1; o < 8; o <<= 1) {
                    m0 = fmaxf(m0, __shfl_xor_sync(0xffffffffu, m0, o));
                    m1 = fmaxf(m1, __shfl_xor_sync(0xffffffffu, m1, o));
                }
                float e0 = expf(s0 - m0), e1 = expf(s1 - m1);
                float t0 = e0, t1 = e1;
#pragma unroll
                for (int o = 1; o < 8; o <<= 1) {
                    t0 += __shfl_xor_sync(0xffffffffu, t0, o);
                    t1 += __shfl_xor_sync(0xffffffffu, t1, o);
                }
                float p0 = e0 / t0, p1 = e1 / t1;
                SP[w * 64 + l]      = p0;
                SP[w * 64 + 32 + l] = p1;
                size_t ab = (size_t)(b0 + w) * 1024 + li * 256 + h * 64;
                attn_out[ab + l]      = p0;
                attn_out[ab + 32 + l] = p1;
                __syncwarp();
                // O = P @ V -> ctx slice
#pragma unroll
                for (int qq = 0; qq < 8; ++qq) {
                    float a0 = 0.f, a1 = 0.f;
#pragma unroll
                    for (int kk2 = 0; kk2 < 8; ++kk2) {
                        float p = SP[w * 64 + qq * 8 + kk2];
                        a0 += p * vB[kk2 * 64 + l];
                        a1 += p * vB[kk2 * 64 + 32 + l];
                    }
                    SCTX[(w * 8 + qq) * 256 + h * 64 + l]      = a0;
                    SCTX[(w * 8 + qq) * 256 + h * 64 + 32 + l] = a1;
                }
            }
        } // heads

        __syncthreads();
        cp_f4(SW, Wo + li * 16384, 4096, tid);
        __syncthreads();
        gemm_block<256, 256, false>(SCTX, SW, bo + li * 64, ST, tid);
        __syncthreads();
        ln_block(ST, SX, g1 + li * 64, be1 + li * 64, w, l);
        __syncthreads();
        cp_f4(SW,        fW1 + li * 4096, 1024, tid);
        cp_f4(SW + 4096, fW2 + li * 4096, 1024, tid);
        __syncthreads();
        gemm_block<64, 64, true>(SX, SW, fb1 + li * 64, ST + 4096, tid);   // h1 = relu(x@fW1+b)
        __syncthreads();
        gemm_block<64, 64, false>(ST + 4096, SW + 4096, fb2 + li * 64, ST, tid); // y2
        __syncthreads();
        ln_block(ST, SX, g2 + li * 64, be2 + li * 64, w, l);
    } // layers

    // ================= Cross attention + heads =================
    // load query tile
    for (int i = tid; i < 512; i += NT)
        SQI[i] = query[(size_t)(b0 + (i >> 6)) * 64 + (i & 63)];

    for (int h = 0; h < HH; ++h) {
        __syncthreads();
        cp_slice(SW,        cWq + h * 64, tid);
        cp_slice(SW + 4096, cWk + h * 64, tid);
        cp_slice(SW + 8192, cWv + h * 64, tid);
        __syncthreads();
        gemm_block<64, 64, false>(SX, SW + 4096, cbk + h * 64, ST,        tid); // Kc
        gemm_block<64, 64, false>(SX, SW + 8192, cbv + h * 64, ST + 4096, tid); // Vc
        // Qc per warp: 1 row x 64 cols
        {
            for (int c = l; c < 64; c += 32) {
                float a = 0.f;
#pragma unroll 8
                for (int k2 = 0; k2 < 64; ++k2) a += SQI[w * 64 + k2] * SW[k2 * 64 + c];
                ST[8192 + w * 64 + c] = a + cbq[h * 64 + c];
            }
        }
        __syncthreads();
        // attention 1x8 per warp
        {
            int j = l >> 2, part = l & 3;
            const float* qrow = ST + 8192 + w * 64;
            const float* kB = ST + w * 512;
            float sc = 0.f;
#pragma unroll
            for (int d = part * 16; d < part * 16 + 16; ++d) sc += qrow[d] * kB[j * 64 + d];
            sc += __shfl_xor_sync(0xffffffffu, sc, 1);
            sc += __shfl_xor_sync(0xffffffffu, sc, 2);
            sc *= SCALE_ATT;
            if (part == 0) SP[w * 8 + j] = sc;
            __syncwarp();
            float mx = -1e30f;
#pragma unroll
            for (int jj = 0; jj < 8; ++jj) mx = fmaxf(mx, SP[w * 8 + jj]);
            float pe[8];
            float ssum = 0.f;
#pragma unroll
            for (int jj = 0; jj < 8; ++jj) { pe[jj] = expf(SP[w * 8 + jj] - mx); ssum += pe[jj]; }
            float inv = 1.f / ssum;
            const float* vB = ST + 4096 + w * 512;
            for (int c = l; c < 64; c += 32) {
                float a = 0.f;
#pragma unroll
                for (int jj = 0; jj < 8; ++jj) a += pe[jj] * vB[jj * 64 + c];
                SCTX[(w * 8) * 256 + h * 64 + c] = a * inv;
            }
        }
    }
    __syncthreads();
    cp_f4(SW, cWo, 4096, tid);
    __syncthreads();
    // ca = relu(ctx @ cWo + cbo); color = relu(ca) @ Wc + bc ; sigma
    {
        const float* ctx = SCTX + w * 2048;  // row w*8, 256 cols
        float a0 = 0.f, a1 = 0.f;
#pragma unroll 8
        for (int k2 = 0; k2 < 256; ++k2) {
            float cv = ctx[k2];
            a0 += cv * SW[k2 * 64 + l];
            a1 += cv * SW[k2 * 64 + 32 + l];
        }
        a0 = fmaxf(a0 + cbo[l], 0.f);
        a1 = fmaxf(a1 + cbo[l + 32], 0.f);
        SCA[w * 64 + l] = a0;
        SCA[w * 64 + 32 + l] = a1;
        __syncwarp();
#pragma unroll
        for (int cc = 0; cc < 3; ++cc) {
            float p = SCA[w * 64 + l] * Wc[l * 3 + cc] + SCA[w * 64 + 32 + l] * Wc[(l + 32) * 3 + cc];
#pragma unroll
            for (int o = 16; o >= 1; o >>= 1) p += __shfl_xor_sync(0xffffffffu, p, o);
            if (l == 0) out[OFF_COLOR + (size_t)(b0 + w) * 3 + cc] = p + bc[cc];
        }
        // sigma = max_s(out) @ Ws + bs
        float m0 = -1e30f, m1 = -1e30f;
#pragma unroll
        for (int s2 = 0; s2 < 8; ++s2) {
            m0 = fmaxf(m0, SX[(w * 8 + s2) * 64 + l]);
            m1 = fmaxf(m1, SX[(w * 8 + s2) * 64 + 32 + l]);
        }
        float p = m0 * Ws[l] + m1 * Ws[l + 32];
#pragma unroll
        for (int o = 16; o >= 1; o >>= 1) p += __shfl_xor_sync(0xffffffffu, p, o);
        if (l == 0) out[OFF_SIGMA + b0 + w] = p + bs[0];
    }
    // write final out activations
    for (int i = tid; i < 4096; i += NT)
        out[OFF_OUT + (size_t)b0 * 512 + i] = SX[i];
}

extern "C" void kernel_launch(void* const* d_in, const int* in_sizes, int n_in,
                              void* d_out, int out_size) {
    (void)in_sizes; (void)n_in; (void)out_size;
    const float* query  = (const float*)d_in[0];
    const float* latent = (const float*)d_in[1];
    const float* W1  = (const float*)d_in[2];
    const float* b1  = (const float*)d_in[3];
    const float* Wq  = (const float*)d_in[4];
    const float* bq  = (const float*)d_in[5];
    const float* Wk  = (const float*)d_in[6];
    const float* bk  = (const float*)d_in[7];
    const float* Wv  = (const float*)d_in[8];
    const float* bv  = (const float*)d_in[9];
    const float* Wo  = (const float*)d_in[10];
    const float* bo  = (const float*)d_in[11];
    const float* fW1 = (const float*)d_in[12];
    const float* fb1 = (const float*)d_in[13];
    const float* fW2 = (const float*)d_in[14];
    const float* fb2 = (const float*)d_in[15];
    const float* g1  = (const float*)d_in[16];
    const float* be1 = (const float*)d_in[17];
    const float* g2  = (const float*)d_in[18];
    const float* be2 = (const float*)d_in[19];
    const float* cWq = (const float*)d_in[20];
    const float* cbq = (const float*)d_in[21];
    const float* cWk = (const float*)d_in[22];
    const float* cbk = (const float*)d_in[23];
    const float* cWv = (const float*)d_in[24];
    const float* cbv = (const float*)d_in[25];
    const float* cWo = (const float*)d_in[26];
    const float* cbo = (const float*)d_in[27];
    const float* Wc  = (const float*)d_in[28];
    const float* bc  = (const float*)d_in[29];
    const float* Ws  = (const float*)d_in[30];
    const float* bs  = (const float*)d_in[31];
    float* out = (float*)d_out;

    const int smem_bytes = SMEM_FLOATS * sizeof(float);
    cudaFuncSetAttribute(radiance_kernel, cudaFuncAttributeMaxDynamicSharedMemorySize, smem_bytes);

    dim3 grid(BB / NB);
    dim3 block(NT);
    radiance_kernel<<<grid, block, smem_bytes>>>(
        query, latent, W1, b1, Wq, bq, Wk, bk, Wv, bv, Wo, bo,
        fW1, fb1, fW2, fb2, g1, be1, g2, be2,
        cWq, cbq, cWk, cbk, cWv, cbv, cWo, cbo, Wc, bc, Ws, bs, out);
}